// round 10
// baseline (speedup 1.0000x reference)
#include <cuda_runtime.h>
#include <cuda_bf16.h>

#define Hdim 128
#define FEATd 32
#define Md 32768
#define Ld 16
#define LDA 132
#define LDW 132
#define ACT 16896                 // 128*132 floats
#define WBO (3*ACT)               // weight double-buffer offset (floats)
#define WBHALF (16*LDW)
#define PIDXO (WBO + 2*WBHALF)
#define SMEM_FLOATS (PIDXO + 256) // 55168 floats = 220672 bytes

typedef unsigned long long u64;

__device__ __forceinline__ u64 ffma2(u64 a, u64 b, u64 c) {
    u64 d; asm("fma.rn.f32x2 %0,%1,%2,%3;" : "=l"(d) : "l"(a), "l"(b), "l"(c)); return d;
}
__device__ __forceinline__ u64 pack2(float x, float y) {
    u64 d; asm("mov.b64 %0,{%1,%2};" : "=l"(d) : "f"(x), "f"(y)); return d;
}
__device__ __forceinline__ float2 unpack2(u64 d) {
    float2 r; asm("mov.b64 {%0,%1},%2;" : "=f"(r.x), "=f"(r.y) : "l"(d)); return r;
}

// acc += A(+B) @ W[:, kofs:kofs+Kp].T ; W global row-major [128 out][wK in],
// streamed in 16-wide K chunks, transposed into double-buffered smem.
template<bool SUM>
__device__ __forceinline__ void do_pass(u64 acc[8][4], int aOff, int bOff,
    const float* __restrict__ Wg, int wK, int kofs, int Kp,
    int tid, int row0, int col0)
{
    extern __shared__ float sm[];
    const int nchunk = Kp >> 4;
    const int i0 = tid, i1 = tid + 256;
    const int n0 = i0 >> 2, kq0 = (i0 & 3) << 2;
    const int n1 = i1 >> 2, kq1 = (i1 & 3) << 2;
    float4 p0 = *(const float4*)(Wg + n0 * wK + kofs + kq0);
    float4 p1 = *(const float4*)(Wg + n1 * wK + kofs + kq1);
    for (int c = 0; c < nchunk; c++) {
        float* buf = sm + WBO + (c & 1) * WBHALF;
        __syncthreads();
        buf[(kq0+0)*LDW + n0] = p0.x; buf[(kq0+1)*LDW + n0] = p0.y;
        buf[(kq0+2)*LDW + n0] = p0.z; buf[(kq0+3)*LDW + n0] = p0.w;
        buf[(kq1+0)*LDW + n1] = p1.x; buf[(kq1+1)*LDW + n1] = p1.y;
        buf[(kq1+2)*LDW + n1] = p1.z; buf[(kq1+3)*LDW + n1] = p1.w;
        if (c + 1 < nchunk) {
            int ko = kofs + ((c + 1) << 4);
            p0 = *(const float4*)(Wg + n0 * wK + ko + kq0);
            p1 = *(const float4*)(Wg + n1 * wK + ko + kq1);
        }
        __syncthreads();
        const float* Ab = sm + aOff + row0 * LDA + (c << 4);
        const float* Bb = sm + bOff + row0 * LDA + (c << 4);
        #pragma unroll
        for (int k4 = 0; k4 < 4; k4++) {
            float af[8][4];
            #pragma unroll
            for (int i = 0; i < 8; i++) {
                float4 av = *(const float4*)(Ab + i * LDA + (k4 << 2));
                if (SUM) {
                    float4 bv = *(const float4*)(Bb + i * LDA + (k4 << 2));
                    av.x += bv.x; av.y += bv.y; av.z += bv.z; av.w += bv.w;
                }
                af[i][0] = av.x; af[i][1] = av.y; af[i][2] = av.z; af[i][3] = av.w;
            }
            #pragma unroll
            for (int kk = 0; kk < 4; kk++) {
                const float* wr = buf + ((k4 << 2) + kk) * LDW + col0;
                u64 w0 = *(const u64*)(wr);
                u64 w1 = *(const u64*)(wr + 2);
                u64 w2 = *(const u64*)(wr + 4);
                u64 w3 = *(const u64*)(wr + 6);
                #pragma unroll
                for (int i = 0; i < 8; i++) {
                    u64 ai = pack2(af[i][kk], af[i][kk]);
                    acc[i][0] = ffma2(ai, w0, acc[i][0]);
                    acc[i][1] = ffma2(ai, w1, acc[i][1]);
                    acc[i][2] = ffma2(ai, w2, acc[i][2]);
                    acc[i][3] = ffma2(ai, w3, acc[i][3]);
                }
            }
        }
    }
}

// MODE 0: relu(A@W.T+b)  1: relu((A+B)@W.T+b)  2: relu([A|A2]@W.T+b)
template<int MODE>
__device__ __noinline__ void mlp_layer(int aOff, int bOff, int a2Off,
    const float* __restrict__ Wg, int wK, int Kp1,
    const float* __restrict__ bias, int dstOff, float* __restrict__ dstG, int tid)
{
    extern __shared__ float sm[];
    const int col0 = (tid & 15) << 3;
    const int row0 = (tid >> 4) << 3;
    u64 acc[8][4];
    {
        u64 b0 = pack2(bias[col0+0], bias[col0+1]);
        u64 b1 = pack2(bias[col0+2], bias[col0+3]);
        u64 b2 = pack2(bias[col0+4], bias[col0+5]);
        u64 b3 = pack2(bias[col0+6], bias[col0+7]);
        #pragma unroll
        for (int i = 0; i < 8; i++) { acc[i][0]=b0; acc[i][1]=b1; acc[i][2]=b2; acc[i][3]=b3; }
    }
    do_pass<MODE==1>(acc, aOff, bOff, Wg, wK, 0, Kp1, tid, row0, col0);
    if (MODE == 2)
        do_pass<false>(acc, a2Off, 0, Wg, wK, Kp1, Kp1, tid, row0, col0);
    __syncthreads();   // all reads of source buffers complete before overwrite
    #pragma unroll
    for (int i = 0; i < 8; i++) {
        float2 v0 = unpack2(acc[i][0]), v1 = unpack2(acc[i][1]);
        float2 v2 = unpack2(acc[i][2]), v3 = unpack2(acc[i][3]);
        float4 fa = make_float4(fmaxf(v0.x,0.f), fmaxf(v0.y,0.f), fmaxf(v1.x,0.f), fmaxf(v1.y,0.f));
        float4 fb = make_float4(fmaxf(v2.x,0.f), fmaxf(v2.y,0.f), fmaxf(v3.x,0.f), fmaxf(v3.y,0.f));
        if (dstG) {
            float* p = dstG + (size_t)(row0 + i) * Hdim + col0;
            *(float4*)p = fa; *(float4*)(p + 4) = fb;
        } else {
            float* p = sm + dstOff + (row0 + i) * LDA + col0;
            *(float4*)p = fa; *(float4*)(p + 4) = fb;
        }
    }
}

__device__ __forceinline__ void gather128(int dstOff, const float* __restrict__ E,
                                          int pidxBase, int tid)
{
    extern __shared__ float sm[];
    const int* pidx = ((const int*)(sm + PIDXO)) + pidxBase;
    #pragma unroll 2
    for (int j = tid; j < 4096; j += 256) {
        int r = j >> 5, c4 = (j & 31) << 2;
        *(float4*)(sm + dstOff + r * LDA + c4) =
            *(const float4*)(E + (size_t)pidx[r] * Hdim + c4);
    }
}

__global__ void __launch_bounds__(256, 1) gnn_level(
    const float* __restrict__ nf,
    const float* __restrict__ emb_w,  const float* __restrict__ emb_b,
    const float* __restrict__ ne0_w,  const float* __restrict__ ne0_b,
    const float* __restrict__ ne_w,   const float* __restrict__ ne_b,
    const float* __restrict__ mpu_w,  const float* __restrict__ mpu_b,
    const float* __restrict__ mpb0_w, const float* __restrict__ mpb0_b,
    const float* __restrict__ mpb_w,  const float* __restrict__ mpb_b,
    const int* __restrict__ parents,
    float* __restrict__ E, int lvl)
{
    extern __shared__ float sm[];
    const int tid = threadIdx.x;
    const size_t rbase = (size_t)lvl * Md + (size_t)blockIdx.x * 128;

    if (lvl > 0) {
        int r = tid & 127, c = tid >> 7;
        ((int*)(sm + PIDXO))[tid] = parents[(rbase + r) * 2 + c];
    }
    // node_feats tile -> X (offset 0)
    for (int j = tid; j < 1024; j += 256) {
        int row = j >> 3, c4 = (j & 7) << 2;
        *(float4*)(sm + row * LDA + c4) = *(const float4*)(nf + (rbase + row) * FEATd + c4);
    }
    __syncthreads();

    if (lvl == 0) {  // E[:M] = base
        mlp_layer<0>(0, -1, -1, emb_w, FEATd, FEATd, emb_b, -1, E + rbase * Hdim, tid);
        return;
    }
    // base tile -> Z (offset 2*ACT)
    mlp_layer<0>(0, -1, -1, emb_w, FEATd, FEATd, emb_b, 2 * ACT, nullptr, tid);

    int P2, P1;
    if (blockIdx.x < 128) {   // unary rows (< MU)
        gather128(0, E, 0, tid);                                     // X = E[p0]
        mlp_layer<0>(0,   -1, -1, mpu_w,          Hdim, Hdim, mpu_b,        ACT, nullptr, tid); // a0->Y
        mlp_layer<0>(ACT, -1, -1, mpu_w + 16384,  Hdim, Hdim, mpu_b + 128,  0,   nullptr, tid); // a1->X
        P2 = ACT; P1 = 0;
        for (int i = 2; i <= 4; i++) {
            mlp_layer<1>(P2, P1, -1, mpu_w + i * 16384, Hdim, Hdim, mpu_b + i * 128, P2, nullptr, tid);
            int t = P2; P2 = P1; P1 = t;
        }
    } else {                  // binary rows
        gather128(0,   E, 0,   tid);                                 // X = E[p0]
        gather128(ACT, E, 128, tid);                                 // Y = E[p1]
        mlp_layer<2>(0, -1, ACT, mpb0_w, 2 * Hdim, Hdim, mpb0_b, 0, nullptr, tid);              // a0->X
        mlp_layer<0>(0, -1, -1,  mpb_w,  Hdim,     Hdim, mpb_b,  ACT, nullptr, tid);            // a1->Y
        P2 = 0; P1 = ACT;
        for (int i = 1; i <= 3; i++) {
            mlp_layer<1>(P2, P1, -1, mpb_w + i * 16384, Hdim, Hdim, mpb_b + i * 128, P2, nullptr, tid);
            int t = P2; P2 = P1; P1 = t;
        }
    }
    // node MLP: x = [base(Z) | redux(P1)], free buffer = P2
    mlp_layer<2>(2 * ACT, -1, P1, ne0_w, 2 * Hdim, Hdim, ne0_b, P2, nullptr, tid);  // a0->P2
    int q2 = P2, q1 = P1;
    mlp_layer<0>(q2, -1, -1, ne_w, Hdim, Hdim, ne_b, q1, nullptr, tid);             // a1->q1
    for (int i = 1; i <= 3; i++) {
        if (i < 3)
            mlp_layer<1>(q2, q1, -1, ne_w + i * 16384, Hdim, Hdim, ne_b + i * 128, q2, nullptr, tid);
        else
            mlp_layer<1>(q2, q1, -1, ne_w + i * 16384, Hdim, Hdim, ne_b + i * 128, -1,
                         E + rbase * Hdim, tid);
        int t = q2; q2 = q1; q1 = t;
    }
}

extern "C" void kernel_launch(void* const* d_in, const int* in_sizes, int n_in,
                              void* d_out, int out_size)
{
    const float* nf     = (const float*)d_in[0];
    const float* emb_w  = (const float*)d_in[1];
    const float* emb_b  = (const float*)d_in[2];
    const float* ne0_w  = (const float*)d_in[3];
    const float* ne0_b  = (const float*)d_in[4];
    const float* ne_w   = (const float*)d_in[5];
    const float* ne_b   = (const float*)d_in[6];
    const float* mpu_w  = (const float*)d_in[7];
    const float* mpu_b  = (const float*)d_in[8];
    const float* mpb0_w = (const float*)d_in[9];
    const float* mpb0_b = (const float*)d_in[10];
    const float* mpb_w  = (const float*)d_in[11];
    const float* mpb_b  = (const float*)d_in[12];
    const int*  parents = (const int*)d_in[13];
    float* E = (float*)d_out;

    const size_t smem = (size_t)SMEM_FLOATS * sizeof(float);
    cudaFuncSetAttribute(gnn_level, cudaFuncAttributeMaxDynamicSharedMemorySize, (int)smem);
    for (int l = 0; l < Ld; l++)
        gnn_level<<<256, 256, smem>>>(nf, emb_w, emb_b, ne0_w, ne0_b, ne_w, ne_b,
                                      mpu_w, mpu_b, mpb0_w, mpb0_b, mpb_w, mpb_b,
                                      parents, E, l);
}

// round 11
// speedup vs baseline: 1.0018x; 1.0018x over previous
#include <cuda_runtime.h>
#include <cuda_bf16.h>

#define Hdim 128
#define FEATd 32
#define Md 32768
#define Ld 16
#define LDA 132
#define LDW 132
#define ACT 16896                 // 128*132 floats
#define WBO (3*ACT)               // weight double-buffer offset (floats)
#define WBHALF (16*LDW)
#define PIDXO (WBO + 2*WBHALF)
#define SMEM_FLOATS (PIDXO + 256) // 55168 floats = 220672 bytes

typedef unsigned long long u64;

__device__ __forceinline__ u64 ffma2(u64 a, u64 b, u64 c) {
    u64 d; asm("fma.rn.f32x2 %0,%1,%2,%3;" : "=l"(d) : "l"(a), "l"(b), "l"(c)); return d;
}
__device__ __forceinline__ u64 pack2(float x, float y) {
    u64 d; asm("mov.b64 %0,{%1,%2};" : "=l"(d) : "f"(x), "f"(y)); return d;
}
__device__ __forceinline__ float2 unpack2(u64 d) {
    float2 r; asm("mov.b64 {%0,%1},%2;" : "=f"(r.x), "=f"(r.y) : "l"(d)); return r;
}

// acc += A(+B) @ W[:, kofs:kofs+Kp].T ; W global row-major [128 out][wK in],
// streamed in 16-wide K chunks, transposed into double-buffered smem.
template<bool SUM>
__device__ __forceinline__ void do_pass(u64 acc[8][4], int aOff, int bOff,
    const float* __restrict__ Wg, int wK, int kofs, int Kp,
    int tid, int row0, int col0)
{
    extern __shared__ float sm[];
    const int nchunk = Kp >> 4;
    const int i0 = tid, i1 = tid + 256;
    const int n0 = i0 >> 2, kq0 = (i0 & 3) << 2;
    const int n1 = i1 >> 2, kq1 = (i1 & 3) << 2;
    float4 p0 = *(const float4*)(Wg + n0 * wK + kofs + kq0);
    float4 p1 = *(const float4*)(Wg + n1 * wK + kofs + kq1);
    for (int c = 0; c < nchunk; c++) {
        float* buf = sm + WBO + (c & 1) * WBHALF;
        __syncthreads();
        buf[(kq0+0)*LDW + n0] = p0.x; buf[(kq0+1)*LDW + n0] = p0.y;
        buf[(kq0+2)*LDW + n0] = p0.z; buf[(kq0+3)*LDW + n0] = p0.w;
        buf[(kq1+0)*LDW + n1] = p1.x; buf[(kq1+1)*LDW + n1] = p1.y;
        buf[(kq1+2)*LDW + n1] = p1.z; buf[(kq1+3)*LDW + n1] = p1.w;
        if (c + 1 < nchunk) {
            int ko = kofs + ((c + 1) << 4);
            p0 = *(const float4*)(Wg + n0 * wK + ko + kq0);
            p1 = *(const float4*)(Wg + n1 * wK + ko + kq1);
        }
        __syncthreads();
        const float* Ab = sm + aOff + row0 * LDA + (c << 4);
        const float* Bb = sm + bOff + row0 * LDA + (c << 4);
        #pragma unroll
        for (int k4 = 0; k4 < 4; k4++) {
            float af[8][4];
            #pragma unroll
            for (int i = 0; i < 8; i++) {
                float4 av = *(const float4*)(Ab + i * LDA + (k4 << 2));
                if (SUM) {
                    float4 bv = *(const float4*)(Bb + i * LDA + (k4 << 2));
                    av.x += bv.x; av.y += bv.y; av.z += bv.z; av.w += bv.w;
                }
                af[i][0] = av.x; af[i][1] = av.y; af[i][2] = av.z; af[i][3] = av.w;
            }
            #pragma unroll
            for (int kk = 0; kk < 4; kk++) {
                const float* wr = buf + ((k4 << 2) + kk) * LDW + col0;
                u64 w0 = *(const u64*)(wr);
                u64 w1 = *(const u64*)(wr + 2);
                u64 w2 = *(const u64*)(wr + 4);
                u64 w3 = *(const u64*)(wr + 6);
                #pragma unroll
                for (int i = 0; i < 8; i++) {
                    u64 ai = pack2(af[i][kk], af[i][kk]);
                    acc[i][0] = ffma2(ai, w0, acc[i][0]);
                    acc[i][1] = ffma2(ai, w1, acc[i][1]);
                    acc[i][2] = ffma2(ai, w2, acc[i][2]);
                    acc[i][3] = ffma2(ai, w3, acc[i][3]);
                }
            }
        }
    }
}

// MODE 0: relu(A@W.T+b)  1: relu((A+B)@W.T+b)  2: relu([A|A2]@W.T+b)
template<int MODE>
__device__ __noinline__ void mlp_layer(int aOff, int bOff, int a2Off,
    const float* __restrict__ Wg, int wK, int Kp1,
    const float* __restrict__ bias, int dstOff, float* __restrict__ dstG, int tid)
{
    extern __shared__ float sm[];
    const int col0 = (tid & 15) << 3;
    const int row0 = (tid >> 4) << 3;
    u64 acc[8][4];
    {
        u64 b0 = pack2(bias[col0+0], bias[col0+1]);
        u64 b1 = pack2(bias[col0+2], bias[col0+3]);
        u64 b2 = pack2(bias[col0+4], bias[col0+5]);
        u64 b3 = pack2(bias[col0+6], bias[col0+7]);
        #pragma unroll
        for (int i = 0; i < 8; i++) { acc[i][0]=b0; acc[i][1]=b1; acc[i][2]=b2; acc[i][3]=b3; }
    }
    do_pass<MODE==1>(acc, aOff, bOff, Wg, wK, 0, Kp1, tid, row0, col0);
    if (MODE == 2)
        do_pass<false>(acc, a2Off, 0, Wg, wK, Kp1, Kp1, tid, row0, col0);
    __syncthreads();   // all reads of source buffers complete before overwrite
    #pragma unroll
    for (int i = 0; i < 8; i++) {
        float2 v0 = unpack2(acc[i][0]), v1 = unpack2(acc[i][1]);
        float2 v2 = unpack2(acc[i][2]), v3 = unpack2(acc[i][3]);
        float4 fa = make_float4(fmaxf(v0.x,0.f), fmaxf(v0.y,0.f), fmaxf(v1.x,0.f), fmaxf(v1.y,0.f));
        float4 fb = make_float4(fmaxf(v2.x,0.f), fmaxf(v2.y,0.f), fmaxf(v3.x,0.f), fmaxf(v3.y,0.f));
        if (dstG) {
            float* p = dstG + (size_t)(row0 + i) * Hdim + col0;
            *(float4*)p = fa; *(float4*)(p + 4) = fb;
        } else {
            float* p = sm + dstOff + (row0 + i) * LDA + col0;
            *(float4*)p = fa; *(float4*)(p + 4) = fb;
        }
    }
}

__device__ __forceinline__ void gather128(int dstOff, const float* __restrict__ E,
                                          int pidxBase, int tid)
{
    extern __shared__ float sm[];
    const int* pidx = ((const int*)(sm + PIDXO)) + pidxBase;
    #pragma unroll 2
    for (int j = tid; j < 4096; j += 256) {
        int r = j >> 5, c4 = (j & 31) << 2;
        *(float4*)(sm + dstOff + r * LDA + c4) =
            *(const float4*)(E + (size_t)pidx[r] * Hdim + c4);
    }
}

__global__ void __launch_bounds__(256, 1) gnn_level(
    const float* __restrict__ nf,
    const float* __restrict__ emb_w,  const float* __restrict__ emb_b,
    const float* __restrict__ ne0_w,  const float* __restrict__ ne0_b,
    const float* __restrict__ ne_w,   const float* __restrict__ ne_b,
    const float* __restrict__ mpu_w,  const float* __restrict__ mpu_b,
    const float* __restrict__ mpb0_w, const float* __restrict__ mpb0_b,
    const float* __restrict__ mpb_w,  const float* __restrict__ mpb_b,
    const int* __restrict__ parents,
    float* __restrict__ E, int lvl)
{
    extern __shared__ float sm[];
    const int tid = threadIdx.x;
    const size_t rbase = (size_t)lvl * Md + (size_t)blockIdx.x * 128;

    if (lvl > 0) {
        int r = tid & 127, c = tid >> 7;
        ((int*)(sm + PIDXO))[tid] = parents[(rbase + r) * 2 + c];
    }
    // node_feats tile -> X (offset 0)
    for (int j = tid; j < 1024; j += 256) {
        int row = j >> 3, c4 = (j & 7) << 2;
        *(float4*)(sm + row * LDA + c4) = *(const float4*)(nf + (rbase + row) * FEATd + c4);
    }
    __syncthreads();

    if (lvl == 0) {  // E[:M] = base
        mlp_layer<0>(0, -1, -1, emb_w, FEATd, FEATd, emb_b, -1, E + rbase * Hdim, tid);
        return;
    }
    // base tile -> Z (offset 2*ACT)
    mlp_layer<0>(0, -1, -1, emb_w, FEATd, FEATd, emb_b, 2 * ACT, nullptr, tid);

    int P2, P1;
    if (blockIdx.x < 128) {   // unary rows (< MU)
        gather128(0, E, 0, tid);                                     // X = E[p0]
        mlp_layer<0>(0,   -1, -1, mpu_w,          Hdim, Hdim, mpu_b,        ACT, nullptr, tid); // a0->Y
        mlp_layer<0>(ACT, -1, -1, mpu_w + 16384,  Hdim, Hdim, mpu_b + 128,  0,   nullptr, tid); // a1->X
        P2 = ACT; P1 = 0;
        for (int i = 2; i <= 4; i++) {
            mlp_layer<1>(P2, P1, -1, mpu_w + i * 16384, Hdim, Hdim, mpu_b + i * 128, P2, nullptr, tid);
            int t = P2; P2 = P1; P1 = t;
        }
    } else {                  // binary rows
        gather128(0,   E, 0,   tid);                                 // X = E[p0]
        gather128(ACT, E, 128, tid);                                 // Y = E[p1]
        mlp_layer<2>(0, -1, ACT, mpb0_w, 2 * Hdim, Hdim, mpb0_b, 0, nullptr, tid);              // a0->X
        mlp_layer<0>(0, -1, -1,  mpb_w,  Hdim,     Hdim, mpb_b,  ACT, nullptr, tid);            // a1->Y
        P2 = 0; P1 = ACT;
        for (int i = 1; i <= 3; i++) {
            mlp_layer<1>(P2, P1, -1, mpb_w + i * 16384, Hdim, Hdim, mpb_b + i * 128, P2, nullptr, tid);
            int t = P2; P2 = P1; P1 = t;
        }
    }
    // node MLP: x = [base(Z) | redux(P1)], free buffer = P2
    mlp_layer<2>(2 * ACT, -1, P1, ne0_w, 2 * Hdim, Hdim, ne0_b, P2, nullptr, tid);  // a0->P2
    int q2 = P2, q1 = P1;
    mlp_layer<0>(q2, -1, -1, ne_w, Hdim, Hdim, ne_b, q1, nullptr, tid);             // a1->q1
    for (int i = 1; i <= 3; i++) {
        if (i < 3)
            mlp_layer<1>(q2, q1, -1, ne_w + i * 16384, Hdim, Hdim, ne_b + i * 128, q2, nullptr, tid);
        else
            mlp_layer<1>(q2, q1, -1, ne_w + i * 16384, Hdim, Hdim, ne_b + i * 128, -1,
                         E + rbase * Hdim, tid);
        int t = q2; q2 = q1; q1 = t;
    }
}

extern "C" void kernel_launch(void* const* d_in, const int* in_sizes, int n_in,
                              void* d_out, int out_size)
{
    const float* nf     = (const float*)d_in[0];
    const float* emb_w  = (const float*)d_in[1];
    const float* emb_b  = (const float*)d_in[2];
    const float* ne0_w  = (const float*)d_in[3];
    const float* ne0_b  = (const float*)d_in[4];
    const float* ne_w   = (const float*)d_in[5];
    const float* ne_b   = (const float*)d_in[6];
    const float* mpu_w  = (const float*)d_in[7];
    const float* mpu_b  = (const float*)d_in[8];
    const float* mpb0_w = (const float*)d_in[9];
    const float* mpb0_b = (const float*)d_in[10];
    const float* mpb_w  = (const float*)d_in[11];
    const float* mpb_b  = (const float*)d_in[12];
    const int*  parents = (const int*)d_in[13];
    float* E = (float*)d_out;

    const size_t smem = (size_t)SMEM_FLOATS * sizeof(float);
    cudaFuncSetAttribute(gnn_level, cudaFuncAttributeMaxDynamicSharedMemorySize, (int)smem);
    for (int l = 0; l < Ld; l++)
        gnn_level<<<256, 256, smem>>>(nf, emb_w, emb_b, ne0_w, ne0_b, ne_w, ne_b,
                                      mpu_w, mpu_b, mpb0_w, mpb0_b, mpb_w, mpb_b,
                                      parents, E, l);
}

// round 12
// speedup vs baseline: 1.1042x; 1.1022x over previous
#include <cuda_runtime.h>
#include <cuda_bf16.h>

#define Hdim 128
#define FEATd 32
#define Md 32768
#define Ld 16
#define LDA 132
#define LDWB 130
#define ACT 16896                 // 128*132 floats
#define WBO (3*ACT)               // weight double-buffer offset (floats)
#define WBHALF (16*LDWB)
#define PIDXO (WBO + 2*WBHALF)
#define SMEM_FLOATS (PIDXO + 256) // 55104 floats = 220416 bytes

typedef unsigned long long u64;

__device__ __forceinline__ u64 ffma2(u64 a, u64 b, u64 c) {
    u64 d; asm("fma.rn.f32x2 %0,%1,%2,%3;" : "=l"(d) : "l"(a), "l"(b), "l"(c)); return d;
}
__device__ __forceinline__ u64 pack2(float x, float y) {
    u64 d; asm("mov.b64 %0,{%1,%2};" : "=l"(d) : "f"(x), "f"(y)); return d;
}
__device__ __forceinline__ float2 unpack2(u64 d) {
    float2 r; asm("mov.b64 {%0,%1},%2;" : "=f"(r.x), "=f"(r.y) : "l"(d)); return r;
}

// acc += A(+B) @ W[:, kofs:kofs+Kp].T ; W global row-major [128 out][wK in],
// streamed in 16-wide K chunks, transposed into double-buffered smem (stride 130).
// Thread owns rows row0..row0+7, column pairs p+{0,32,64,96}. All W LDS.64 and
// epilogue stores are bank-conflict-free under this mapping.
template<bool SUM>
__device__ __forceinline__ void do_pass(u64 acc[8][4], int aOff, int bOff,
    const float* __restrict__ Wg, int wK, int kofs, int Kp,
    int tid, int row0, int p)
{
    extern __shared__ float sm[];
    const int nchunk = Kp >> 4;
    const int i0 = tid, i1 = tid + 256;
    const int n0 = i0 >> 2, kq0 = (i0 & 3) << 2;
    const int n1 = i1 >> 2, kq1 = (i1 & 3) << 2;
    float4 p0 = *(const float4*)(Wg + n0 * wK + kofs + kq0);
    float4 p1 = *(const float4*)(Wg + n1 * wK + kofs + kq1);
    for (int c = 0; c < nchunk; c++) {
        float* buf = sm + WBO + (c & 1) * WBHALF;
        __syncthreads();
        buf[(kq0+0)*LDWB + n0] = p0.x; buf[(kq0+1)*LDWB + n0] = p0.y;
        buf[(kq0+2)*LDWB + n0] = p0.z; buf[(kq0+3)*LDWB + n0] = p0.w;
        buf[(kq1+0)*LDWB + n1] = p1.x; buf[(kq1+1)*LDWB + n1] = p1.y;
        buf[(kq1+2)*LDWB + n1] = p1.z; buf[(kq1+3)*LDWB + n1] = p1.w;
        if (c + 1 < nchunk) {
            int ko = kofs + ((c + 1) << 4);
            p0 = *(const float4*)(Wg + n0 * wK + ko + kq0);
            p1 = *(const float4*)(Wg + n1 * wK + ko + kq1);
        }
        __syncthreads();
        const float* Ab = sm + aOff + row0 * LDA + (c << 4);
        const float* Bb = sm + bOff + row0 * LDA + (c << 4);
        #pragma unroll
        for (int k4 = 0; k4 < 4; k4++) {
            float af[8][4];
            #pragma unroll
            for (int i = 0; i < 8; i++) {
                float4 av = *(const float4*)(Ab + i * LDA + (k4 << 2));
                if (SUM) {
                    float4 bv = *(const float4*)(Bb + i * LDA + (k4 << 2));
                    av.x += bv.x; av.y += bv.y; av.z += bv.z; av.w += bv.w;
                }
                af[i][0] = av.x; af[i][1] = av.y; af[i][2] = av.z; af[i][3] = av.w;
            }
            #pragma unroll
            for (int kk = 0; kk < 4; kk++) {
                const float* wr = buf + ((k4 << 2) + kk) * LDWB + p;
                u64 w0 = *(const u64*)(wr);
                u64 w1 = *(const u64*)(wr + 32);
                u64 w2 = *(const u64*)(wr + 64);
                u64 w3 = *(const u64*)(wr + 96);
                #pragma unroll
                for (int i = 0; i < 8; i++) {
                    u64 ai = pack2(af[i][kk], af[i][kk]);
                    acc[i][0] = ffma2(ai, w0, acc[i][0]);
                    acc[i][1] = ffma2(ai, w1, acc[i][1]);
                    acc[i][2] = ffma2(ai, w2, acc[i][2]);
                    acc[i][3] = ffma2(ai, w3, acc[i][3]);
                }
            }
        }
    }
}

// MODE 0: relu(A@W.T+b)  1: relu((A+B)@W.T+b)  2: relu([A|A2]@W.T+b)
template<int MODE>
__device__ __noinline__ void mlp_layer(int aOff, int bOff, int a2Off,
    const float* __restrict__ Wg, int wK, int Kp1,
    const float* __restrict__ bias, int dstOff, float* __restrict__ dstG, int tid)
{
    extern __shared__ float sm[];
    const int p = (tid & 15) << 1;
    const int row0 = (tid >> 4) << 3;
    u64 acc[8][4];
    {
        u64 b0 = pack2(bias[p +  0], bias[p +  1]);
        u64 b1 = pack2(bias[p + 32], bias[p + 33]);
        u64 b2 = pack2(bias[p + 64], bias[p + 65]);
        u64 b3 = pack2(bias[p + 96], bias[p + 97]);
        #pragma unroll
        for (int i = 0; i < 8; i++) { acc[i][0]=b0; acc[i][1]=b1; acc[i][2]=b2; acc[i][3]=b3; }
    }
    do_pass<MODE==1>(acc, aOff, bOff, Wg, wK, 0, Kp1, tid, row0, p);
    if (MODE == 2)
        do_pass<false>(acc, a2Off, 0, Wg, wK, Kp1, Kp1, tid, row0, p);
    __syncthreads();   // all reads of source buffers complete before overwrite
    #pragma unroll
    for (int i = 0; i < 8; i++) {
        #pragma unroll
        for (int j = 0; j < 4; j++) {
            float2 v = unpack2(acc[i][j]);
            v.x = fmaxf(v.x, 0.f); v.y = fmaxf(v.y, 0.f);
            if (dstG) *(float2*)(dstG + (size_t)(row0 + i) * Hdim + p + 32*j) = v;
            else      *(float2*)(sm + dstOff + (row0 + i) * LDA + p + 32*j) = v;
        }
    }
}

__device__ __forceinline__ void gather128(int dstOff, const float* __restrict__ E,
                                          int pidxBase, int tid)
{
    extern __shared__ float sm[];
    const int* pidx = ((const int*)(sm + PIDXO)) + pidxBase;
    #pragma unroll 2
    for (int j = tid; j < 4096; j += 256) {
        int r = j >> 5, c4 = (j & 31) << 2;
        *(float4*)(sm + dstOff + r * LDA + c4) =
            *(const float4*)(E + (size_t)pidx[r] * Hdim + c4);
    }
}

__global__ void __launch_bounds__(256, 1) gnn_level(
    const float* __restrict__ nf,
    const float* __restrict__ emb_w,  const float* __restrict__ emb_b,
    const float* __restrict__ ne0_w,  const float* __restrict__ ne0_b,
    const float* __restrict__ ne_w,   const float* __restrict__ ne_b,
    const float* __restrict__ mpu_w,  const float* __restrict__ mpu_b,
    const float* __restrict__ mpb0_w, const float* __restrict__ mpb0_b,
    const float* __restrict__ mpb_w,  const float* __restrict__ mpb_b,
    const int* __restrict__ parents,
    float* __restrict__ E, int lvl)
{
    extern __shared__ float sm[];
    const int tid = threadIdx.x;
    const size_t rbase = (size_t)lvl * Md + (size_t)blockIdx.x * 128;

    if (lvl > 0) {
        int r = tid & 127, c = tid >> 7;
        ((int*)(sm + PIDXO))[tid] = parents[(rbase + r) * 2 + c];
    }
    // node_feats tile -> X (offset 0)
    for (int j = tid; j < 1024; j += 256) {
        int row = j >> 3, c4 = (j & 7) << 2;
        *(float4*)(sm + row * LDA + c4) = *(const float4*)(nf + (rbase + row) * FEATd + c4);
    }
    __syncthreads();

    if (lvl == 0) {  // E[:M] = base
        mlp_layer<0>(0, -1, -1, emb_w, FEATd, FEATd, emb_b, -1, E + rbase * Hdim, tid);
        return;
    }
    // base tile -> Z (offset 2*ACT)
    mlp_layer<0>(0, -1, -1, emb_w, FEATd, FEATd, emb_b, 2 * ACT, nullptr, tid);

    int P2, P1;
    if (blockIdx.x < 128) {   // unary rows (< MU)
        gather128(0, E, 0, tid);                                     // X = E[p0]
        mlp_layer<0>(0,   -1, -1, mpu_w,          Hdim, Hdim, mpu_b,        ACT, nullptr, tid); // a0->Y
        mlp_layer<0>(ACT, -1, -1, mpu_w + 16384,  Hdim, Hdim, mpu_b + 128,  0,   nullptr, tid); // a1->X
        P2 = ACT; P1 = 0;
        for (int i = 2; i <= 4; i++) {
            mlp_layer<1>(P2, P1, -1, mpu_w + i * 16384, Hdim, Hdim, mpu_b + i * 128, P2, nullptr, tid);
            int t = P2; P2 = P1; P1 = t;
        }
    } else {                  // binary rows
        gather128(0,   E, 0,   tid);                                 // X = E[p0]
        gather128(ACT, E, 128, tid);                                 // Y = E[p1]
        mlp_layer<2>(0, -1, ACT, mpb0_w, 2 * Hdim, Hdim, mpb0_b, 0, nullptr, tid);              // a0->X
        mlp_layer<0>(0, -1, -1,  mpb_w,  Hdim,     Hdim, mpb_b,  ACT, nullptr, tid);            // a1->Y
        P2 = 0; P1 = ACT;
        for (int i = 1; i <= 3; i++) {
            mlp_layer<1>(P2, P1, -1, mpb_w + i * 16384, Hdim, Hdim, mpb_b + i * 128, P2, nullptr, tid);
            int t = P2; P2 = P1; P1 = t;
        }
    }
    // node MLP: x = [base(Z) | redux(P1)], free buffer = P2
    mlp_layer<2>(2 * ACT, -1, P1, ne0_w, 2 * Hdim, Hdim, ne0_b, P2, nullptr, tid);  // a0->P2
    int q2 = P2, q1 = P1;
    mlp_layer<0>(q2, -1, -1, ne_w, Hdim, Hdim, ne_b, q1, nullptr, tid);             // a1->q1
    for (int i = 1; i <= 3; i++) {
        if (i < 3)
            mlp_layer<1>(q2, q1, -1, ne_w + i * 16384, Hdim, Hdim, ne_b + i * 128, q2, nullptr, tid);
        else
            mlp_layer<1>(q2, q1, -1, ne_w + i * 16384, Hdim, Hdim, ne_b + i * 128, -1,
                         E + rbase * Hdim, tid);
        int t = q2; q2 = q1; q1 = t;
    }
}

extern "C" void kernel_launch(void* const* d_in, const int* in_sizes, int n_in,
                              void* d_out, int out_size)
{
    const float* nf     = (const float*)d_in[0];
    const float* emb_w  = (const float*)d_in[1];
    const float* emb_b  = (const float*)d_in[2];
    const float* ne0_w  = (const float*)d_in[3];
    const float* ne0_b  = (const float*)d_in[4];
    const float* ne_w   = (const float*)d_in[5];
    const float* ne_b   = (const float*)d_in[6];
    const float* mpu_w  = (const float*)d_in[7];
    const float* mpu_b  = (const float*)d_in[8];
    const float* mpb0_w = (const float*)d_in[9];
    const float* mpb0_b = (const float*)d_in[10];
    const float* mpb_w  = (const float*)d_in[11];
    const float* mpb_b  = (const float*)d_in[12];
    const int*  parents = (const int*)d_in[13];
    float* E = (float*)d_out;

    const size_t smem = (size_t)SMEM_FLOATS * sizeof(float);
    cudaFuncSetAttribute(gnn_level, cudaFuncAttributeMaxDynamicSharedMemorySize, (int)smem);
    for (int l = 0; l < Ld; l++)
        gnn_level<<<256, 256, smem>>>(nf, emb_w, emb_b, ne0_w, ne0_b, ne_w, ne_b,
                                      mpu_w, mpu_b, mpb0_w, mpb0_b, mpb_w, mpb_b,
                                      parents, E, l);
}